// round 4
// baseline (speedup 1.0000x reference)
#include <cuda_runtime.h>
#include <cstdint>

// out = relu( row_mask ? (features + residuals[0] + residuals[1]) : 0 )
// features:  (256, 128, 1024) f32
// residuals: (2, 256, 128, 1024) f32
// mol_slice: (256, 2) int64 OR int32 (runtime-detected)
//
// 4 consecutive rows per block (same batch: 4 | 128), 256 threads, one float4
// column per thread. Depth-2 software pipeline over rows: max 2 rows of loads
// live (~48 regs) -> higher occupancy than full front-batch, same MLP.
// Streaming (.cs) loads/stores: every byte touched exactly once.

#define BATCH 256
#define MAX_ATOM 128
#define N_FEAT 1024
#define THREADS 256        // N_FEAT / 4
#define ROWS_PER_BLK 4

__device__ __forceinline__ float4 ldcs4(const float4* p) {
    float4 v;
    asm volatile("ld.global.cs.v4.f32 {%0,%1,%2,%3}, [%4];"
                 : "=f"(v.x), "=f"(v.y), "=f"(v.z), "=f"(v.w) : "l"(p));
    return v;
}

__device__ __forceinline__ void stcs4(float4* p, float4 v) {
    asm volatile("st.global.cs.v4.f32 [%0], {%1,%2,%3,%4};"
                 :: "l"(p), "f"(v.x), "f"(v.y), "f"(v.z), "f"(v.w) : "memory");
}

__global__ __launch_bounds__(THREADS)
void dense_block_end_kernel(const float* __restrict__ features,
                            const float* __restrict__ residuals,
                            const void*  __restrict__ mol_slice,
                            float* __restrict__ out)
{
    const int row0 = blockIdx.x * ROWS_PER_BLK;
    const int b    = row0 >> 7;                  // / MAX_ATOM
    const int a0   = row0 & (MAX_ATOM - 1);

    // mol_slice dtype sniff:
    //   int32: [M0, 1024, M1, 1024, ...] -> word[1] == 1024
    //   int64: [M0, 0, 1024, 0, ...]     -> word[1] == 0 (hi word, M <= 128)
    const int* ms32 = (const int*)mol_slice;
    int n_atoms;
    if (ms32[1] == N_FEAT) {
        n_atoms = ms32[2 * b];
    } else {
        n_atoms = (int)((const long long*)mol_slice)[2 * b];
    }

    const size_t res_stride = (size_t)BATCH * MAX_ATOM * N_FEAT;
    const size_t base0 = (size_t)row0 * N_FEAT + threadIdx.x * 4;

    // Depth-2 pipeline: slots 0/1 hold loads for rows i and i+1.
    float4 f[2], r0[2], r1[2];

    #define LOADROW(i)                                                          \
        do {                                                                    \
            if ((a0 + (i)) < n_atoms) {                                         \
                const size_t _b = base0 + (size_t)(i) * N_FEAT;                 \
                f[(i) & 1]  = ldcs4((const float4*)(features + _b));            \
                r0[(i) & 1] = ldcs4((const float4*)(residuals + _b));           \
                r1[(i) & 1] = ldcs4((const float4*)(residuals + res_stride + _b)); \
            }                                                                   \
        } while (0)

    #define STORROW(i)                                                          \
        do {                                                                    \
            const size_t _b = base0 + (size_t)(i) * N_FEAT;                     \
            float4 v = make_float4(0.f, 0.f, 0.f, 0.f);                         \
            if ((a0 + (i)) < n_atoms) {                                         \
                const int s = (i) & 1;                                          \
                v.x = fmaxf(f[s].x + r0[s].x + r1[s].x, 0.f);                   \
                v.y = fmaxf(f[s].y + r0[s].y + r1[s].y, 0.f);                   \
                v.z = fmaxf(f[s].z + r0[s].z + r1[s].z, 0.f);                   \
                v.w = fmaxf(f[s].w + r0[s].w + r1[s].w, 0.f);                   \
            }                                                                   \
            stcs4((float4*)(out + _b), v);                                      \
        } while (0)

    LOADROW(0);
    LOADROW(1);
    STORROW(0);
    LOADROW(2);
    STORROW(1);
    LOADROW(3);
    STORROW(2);
    STORROW(3);

    #undef LOADROW
    #undef STORROW
}

extern "C" void kernel_launch(void* const* d_in, const int* in_sizes, int n_in,
                              void* d_out, int out_size)
{
    const float* features  = (const float*)d_in[0];
    const float* residuals = (const float*)d_in[1];
    const void*  mol_slice = d_in[2];
    float* out = (float*)d_out;

    dense_block_end_kernel<<<(BATCH * MAX_ATOM) / ROWS_PER_BLK, THREADS>>>(
        features, residuals, mol_slice, out);
}

// round 5
// speedup vs baseline: 1.0201x; 1.0201x over previous
#include <cuda_runtime.h>
#include <cstdint>

// out = relu( row_mask ? (features + residuals[0] + residuals[1]) : 0 )
// features:  (256, 128, 1024) f32
// residuals: (2, 256, 128, 1024) f32
// mol_slice: (256, 2) int64 OR int32 (runtime-detected)
//
// 2 consecutive rows per block (same batch: 2 | 128), 128 threads, one
// 8-float (256-bit) slot per thread — Blackwell v8 global ld/st.
// All 6 loads front-batched (independent 256-bit LDGs), then compute+store.
// Masked rows: zero store only, no loads.

#define BATCH 256
#define MAX_ATOM 128
#define N_FEAT 1024
#define THREADS 128        // N_FEAT / 8
#define ROWS_PER_BLK 2

struct f8 { float v[8]; };

__device__ __forceinline__ f8 ldnc8(const float* p) {
    f8 r;
    asm volatile("ld.global.nc.v8.f32 {%0,%1,%2,%3,%4,%5,%6,%7}, [%8];"
                 : "=f"(r.v[0]), "=f"(r.v[1]), "=f"(r.v[2]), "=f"(r.v[3]),
                   "=f"(r.v[4]), "=f"(r.v[5]), "=f"(r.v[6]), "=f"(r.v[7])
                 : "l"(p));
    return r;
}

__device__ __forceinline__ void stcs8(float* p, const f8& r) {
    asm volatile("st.global.cs.v8.f32 [%0], {%1,%2,%3,%4,%5,%6,%7,%8};"
                 :: "l"(p),
                    "f"(r.v[0]), "f"(r.v[1]), "f"(r.v[2]), "f"(r.v[3]),
                    "f"(r.v[4]), "f"(r.v[5]), "f"(r.v[6]), "f"(r.v[7])
                 : "memory");
}

__global__ __launch_bounds__(THREADS)
void dense_block_end_kernel(const float* __restrict__ features,
                            const float* __restrict__ residuals,
                            const void*  __restrict__ mol_slice,
                            float* __restrict__ out)
{
    const int row0 = blockIdx.x * ROWS_PER_BLK;
    const int b    = row0 >> 7;                  // / MAX_ATOM
    const int a0   = row0 & (MAX_ATOM - 1);

    // mol_slice dtype sniff:
    //   int32: [M0, 1024, M1, 1024, ...] -> word[1] == 1024
    //   int64: [M0, 0, 1024, 0, ...]     -> word[1] == 0 (hi word, M <= 128)
    const int* ms32 = (const int*)mol_slice;
    int n_atoms;
    if (ms32[1] == N_FEAT) {
        n_atoms = ms32[2 * b];
    } else {
        n_atoms = (int)((const long long*)mol_slice)[2 * b];
    }

    const size_t res_stride = (size_t)BATCH * MAX_ATOM * N_FEAT;
    const size_t base0 = (size_t)row0 * N_FEAT + threadIdx.x * 8;

    // Front-batch ALL loads (up to 6 independent 256-bit LDGs), then compute.
    f8 f[ROWS_PER_BLK], r0[ROWS_PER_BLK], r1[ROWS_PER_BLK];
    bool act[ROWS_PER_BLK];

    #pragma unroll
    for (int i = 0; i < ROWS_PER_BLK; i++) {
        act[i] = (a0 + i) < n_atoms;
        const size_t base = base0 + (size_t)i * N_FEAT;
        if (act[i]) {
            f[i]  = ldnc8(features + base);
            r0[i] = ldnc8(residuals + base);
            r1[i] = ldnc8(residuals + res_stride + base);
        }
    }

    #pragma unroll
    for (int i = 0; i < ROWS_PER_BLK; i++) {
        const size_t base = base0 + (size_t)i * N_FEAT;
        f8 v;
        #pragma unroll
        for (int j = 0; j < 8; j++) v.v[j] = 0.f;
        if (act[i]) {
            #pragma unroll
            for (int j = 0; j < 8; j++)
                v.v[j] = fmaxf(f[i].v[j] + r0[i].v[j] + r1[i].v[j], 0.f);
        }
        stcs8(out + base, v);
    }
}

extern "C" void kernel_launch(void* const* d_in, const int* in_sizes, int n_in,
                              void* d_out, int out_size)
{
    const float* features  = (const float*)d_in[0];
    const float* residuals = (const float*)d_in[1];
    const void*  mol_slice = d_in[2];
    float* out = (float*)d_out;

    dense_block_end_kernel<<<(BATCH * MAX_ATOM) / ROWS_PER_BLK, THREADS>>>(
        features, residuals, mol_slice, out);
}

// round 6
// speedup vs baseline: 1.0292x; 1.0089x over previous
#include <cuda_runtime.h>
#include <cstdint>

// out = relu( row_mask ? (features + residuals[0] + residuals[1]) : 0 )
// features:  (256, 128, 1024) f32
// residuals: (2, 256, 128, 1024) f32
// mol_slice: (256, 2) int64 OR int32 (runtime-detected)
//
// 4 consecutive rows per block (same batch: 4 | 128), 128 threads, one
// 8-float (256-bit) slot per thread. ALL 12 v8 loads front-batched
// (384 bytes in flight per thread) -> deepest DRAM read bursts.
// Masked rows: zero store only, no loads.

#define BATCH 256
#define MAX_ATOM 128
#define N_FEAT 1024
#define THREADS 128        // N_FEAT / 8
#define ROWS_PER_BLK 4

struct f8 { float v[8]; };

__device__ __forceinline__ f8 ldnc8(const float* p) {
    f8 r;
    asm volatile("ld.global.nc.v8.f32 {%0,%1,%2,%3,%4,%5,%6,%7}, [%8];"
                 : "=f"(r.v[0]), "=f"(r.v[1]), "=f"(r.v[2]), "=f"(r.v[3]),
                   "=f"(r.v[4]), "=f"(r.v[5]), "=f"(r.v[6]), "=f"(r.v[7])
                 : "l"(p));
    return r;
}

__device__ __forceinline__ void stcs8(float* p, const f8& r) {
    asm volatile("st.global.cs.v8.f32 [%0], {%1,%2,%3,%4,%5,%6,%7,%8};"
                 :: "l"(p),
                    "f"(r.v[0]), "f"(r.v[1]), "f"(r.v[2]), "f"(r.v[3]),
                    "f"(r.v[4]), "f"(r.v[5]), "f"(r.v[6]), "f"(r.v[7])
                 : "memory");
}

__global__ __launch_bounds__(THREADS)
void dense_block_end_kernel(const float* __restrict__ features,
                            const float* __restrict__ residuals,
                            const void*  __restrict__ mol_slice,
                            float* __restrict__ out)
{
    const int row0 = blockIdx.x * ROWS_PER_BLK;
    const int b    = row0 >> 7;                  // / MAX_ATOM
    const int a0   = row0 & (MAX_ATOM - 1);

    // mol_slice dtype sniff:
    //   int32: [M0, 1024, M1, 1024, ...] -> word[1] == 1024
    //   int64: [M0, 0, 1024, 0, ...]     -> word[1] == 0 (hi word, M <= 128)
    const int* ms32 = (const int*)mol_slice;
    int n_atoms;
    if (ms32[1] == N_FEAT) {
        n_atoms = ms32[2 * b];
    } else {
        n_atoms = (int)((const long long*)mol_slice)[2 * b];
    }

    const size_t res_stride = (size_t)BATCH * MAX_ATOM * N_FEAT;
    const size_t base0 = (size_t)row0 * N_FEAT + threadIdx.x * 8;

    // Front-batch ALL loads (up to 12 independent 256-bit LDGs), then compute.
    f8 f[ROWS_PER_BLK], r0[ROWS_PER_BLK], r1[ROWS_PER_BLK];
    bool act[ROWS_PER_BLK];

    #pragma unroll
    for (int i = 0; i < ROWS_PER_BLK; i++) {
        act[i] = (a0 + i) < n_atoms;
        const size_t base = base0 + (size_t)i * N_FEAT;
        if (act[i]) {
            f[i]  = ldnc8(features + base);
            r0[i] = ldnc8(residuals + base);
            r1[i] = ldnc8(residuals + res_stride + base);
        }
    }

    #pragma unroll
    for (int i = 0; i < ROWS_PER_BLK; i++) {
        const size_t base = base0 + (size_t)i * N_FEAT;
        f8 v;
        #pragma unroll
        for (int j = 0; j < 8; j++) v.v[j] = 0.f;
        if (act[i]) {
            #pragma unroll
            for (int j = 0; j < 8; j++)
                v.v[j] = fmaxf(f[i].v[j] + r0[i].v[j] + r1[i].v[j], 0.f);
        }
        stcs8(out + base, v);
    }
}

extern "C" void kernel_launch(void* const* d_in, const int* in_sizes, int n_in,
                              void* d_out, int out_size)
{
    const float* features  = (const float*)d_in[0];
    const float* residuals = (const float*)d_in[1];
    const void*  mol_slice = d_in[2];
    float* out = (float*)d_out;

    dense_block_end_kernel<<<(BATCH * MAX_ATOM) / ROWS_PER_BLK, THREADS>>>(
        features, residuals, mol_slice, out);
}